// round 1
// baseline (speedup 1.0000x reference)
#include <cuda_runtime.h>
#include <cstdint>

// ---------------------------------------------------------------------------
// AudioSNN: conv1+spike+pool -> conv2+spike+pool -> fc1 (once) -> 25-step LIF
// All fp32 (binary-spike thresholds: any precision loss flips spikes -> fail).
// ---------------------------------------------------------------------------

#define BATCH 1024
#define NSTEPS 25

// scratch (device globals: no allocation allowed in kernel_launch)
__device__ float g_c1[BATCH * 32 * 32 * 16];   // pooled spikes after conv1: [B][32][32][16]
__device__ float g_xflat[BATCH * 8192];        // pooled spikes after conv2, flattened
__device__ float g_cur3[BATCH * 256];          // fc1 output (constant over timesteps)

// ---------------------------------------------------------------------------
// Kernel 1: conv1 (1->32, 3x3 SAME) + spike(>1) + avgpool2  -> g_c1
// one CTA per image, 256 threads
// ---------------------------------------------------------------------------
__global__ void __launch_bounds__(256) conv1_kernel(const float* __restrict__ x,
                                                    const float* __restrict__ w1,
                                                    const float* __restrict__ b1) {
    __shared__ float sIn[66 * 34];   // padded 64x32 image
    __shared__ float sW[32 * 9];
    __shared__ float sB[32];
    const int t = threadIdx.x;
    const int img = blockIdx.x;

    for (int i = t; i < 66 * 34; i += 256) sIn[i] = 0.f;
    for (int i = t; i < 288; i += 256) sW[i] = w1[i];
    if (t < 32) sB[t] = b1[t];
    __syncthreads();

    const float* xi = x + img * 2048;
    for (int i = t; i < 2048; i += 256) {
        int y = i >> 5, xc = i & 31;
        sIn[(y + 1) * 34 + (xc + 1)] = xi[i];
    }
    __syncthreads();

    // 512 pooled cells (32x16); each thread does 2 cells x 32 channels
    for (int cellBase = 0; cellBase < 512; cellBase += 256) {
        int cell = cellBase + t;
        int ph = cell >> 4, pw = cell & 15;
        float in[4][4];
#pragma unroll
        for (int r = 0; r < 4; r++)
#pragma unroll
            for (int c = 0; c < 4; c++)
                in[r][c] = sIn[(2 * ph + r) * 34 + (2 * pw + c)];

        for (int ch = 0; ch < 32; ch++) {
            float wv[9];
#pragma unroll
            for (int k = 0; k < 9; k++) wv[k] = sW[ch * 9 + k];
            float bb = sB[ch];
            float cnt = 0.f;
#pragma unroll
            for (int dy = 0; dy < 2; dy++)
#pragma unroll
                for (int dx = 0; dx < 2; dx++) {
                    float s = bb;
#pragma unroll
                    for (int ky = 0; ky < 3; ky++)
#pragma unroll
                        for (int kx = 0; kx < 3; kx++)
                            s += wv[ky * 3 + kx] * in[dy + ky][dx + kx];
                    cnt += (s > 1.f) ? 1.f : 0.f;
                }
            g_c1[((img * 32 + ch) * 32 + ph) * 16 + pw] = cnt * 0.25f;
        }
    }
}

// ---------------------------------------------------------------------------
// Kernel 2: conv2 (32->64, 3x3 SAME) + spike(>1) + avgpool2 -> g_xflat
// one CTA per image; full image + all weights in smem (~177 KB)
// ---------------------------------------------------------------------------
#define C2_SIN   (32 * 34 * 18)      // 19584 padded input
#define C2_SW    (64 * 32 * 12)      // 24576 weights padded to 12/tap-group
#define C2_SMEM_BYTES ((C2_SIN + C2_SW + 64) * 4)

__global__ void __launch_bounds__(256, 1) conv2_kernel(const float* __restrict__ w2,
                                                       const float* __restrict__ b2) {
    extern __shared__ float sm[];
    float* sIn = sm;                 // [ci][34][18]
    float* sW  = sm + C2_SIN;        // [(oc*32+ci)*12 + k]
    float* sB  = sW + C2_SW;         // [64]
    const int t = threadIdx.x;
    const int img = blockIdx.x;

    for (int i = t; i < C2_SIN; i += 256) sIn[i] = 0.f;
    __syncthreads();

    const float* c1p = g_c1 + img * 16384;
    for (int i = t; i < 16384; i += 256) {
        int ci = i >> 9, rem = i & 511;
        int h = rem >> 4, w = rem & 15;
        sIn[ci * 612 + (h + 1) * 18 + (w + 1)] = c1p[i];
    }
    for (int i = t; i < 18432; i += 256) {
        int oc = i / 288, rem = i % 288;
        int ci = rem / 9, k = rem % 9;
        sW[(oc * 32 + ci) * 12 + k] = w2[i];
    }
    if (t < 64) sB[t] = b2[t];
    __syncthreads();

    const int cell = t & 127, half = t >> 7;
    const int ph = cell >> 3, pw = cell & 7;
    const int inbase = 2 * ph * 18 + 2 * pw;
    float* xout = g_xflat + img * 8192;

    for (int ocb = 0; ocb < 4; ocb++) {
        const int ocbase = half * 32 + ocb * 8;
        float acc[8][4];
#pragma unroll
        for (int o = 0; o < 8; o++)
#pragma unroll
            for (int q = 0; q < 4; q++) acc[o][q] = 0.f;

        for (int ci = 0; ci < 32; ci++) {
            float in[4][4];
            const float* ip = sIn + ci * 612 + inbase;
#pragma unroll
            for (int r = 0; r < 4; r++) {
                float2 p0 = *(const float2*)(ip + r * 18);
                float2 p1 = *(const float2*)(ip + r * 18 + 2);
                in[r][0] = p0.x; in[r][1] = p0.y; in[r][2] = p1.x; in[r][3] = p1.y;
            }
            const float* wp = sW + (ocbase * 32 + ci) * 12;
#pragma unroll
            for (int o = 0; o < 8; o++) {
                const float* wo = wp + o * 384;
                float4 wa = *(const float4*)wo;
                float4 wb = *(const float4*)(wo + 4);
                float w8 = wo[8];
#pragma unroll
                for (int dy = 0; dy < 2; dy++)
#pragma unroll
                    for (int dx = 0; dx < 2; dx++) {
                        float s = acc[o][dy * 2 + dx];
                        s += wa.x * in[dy + 0][dx + 0];
                        s += wa.y * in[dy + 0][dx + 1];
                        s += wa.z * in[dy + 0][dx + 2];
                        s += wa.w * in[dy + 1][dx + 0];
                        s += wb.x * in[dy + 1][dx + 1];
                        s += wb.y * in[dy + 1][dx + 2];
                        s += wb.z * in[dy + 2][dx + 0];
                        s += wb.w * in[dy + 2][dx + 1];
                        s += w8   * in[dy + 2][dx + 2];
                        acc[o][dy * 2 + dx] = s;
                    }
            }
        }
#pragma unroll
        for (int o = 0; o < 8; o++) {
            int oc = ocbase + o;
            float bv = sB[oc];
            float cnt = 0.f;
#pragma unroll
            for (int q = 0; q < 4; q++) cnt += (acc[o][q] + bv > 1.f) ? 1.f : 0.f;
            xout[oc * 128 + ph * 8 + pw] = cnt * 0.25f;
        }
    }
}

// ---------------------------------------------------------------------------
// Kernel 3: fc1 GEMM  cur3[b][n] = sum_k xflat[b][k]*W[n][k] + bias[n]
// tile 64(rows) x 32(cols), grid (16,8)=128 CTAs, 256 thr, 4x2 micro
// ---------------------------------------------------------------------------
__global__ void __launch_bounds__(256) fc1_kernel(const float* __restrict__ W,
                                                  const float* __restrict__ bias) {
    __shared__ float sA[64][64];   // [k][row]
    __shared__ float sW2[64][32];  // [k][n]
    const int t = threadIdx.x;
    const int row0 = blockIdx.x * 64;
    const int n0 = blockIdx.y * 32;
    const int tx = t & 15, ty = t >> 4;

    const int lr = t >> 2, lk = (t & 3) * 16;   // A loader: row, k-chunk
    const int wn = t >> 3, wk = (t & 7) * 8;    // W loader: n, k-chunk

    float acc[4][2];
#pragma unroll
    for (int r = 0; r < 4; r++) { acc[r][0] = 0.f; acc[r][1] = 0.f; }

    for (int k0 = 0; k0 < 8192; k0 += 64) {
#pragma unroll
        for (int j = 0; j < 4; j++) {
            float4 v = *(const float4*)&g_xflat[(row0 + lr) * 8192 + k0 + lk + 4 * j];
            sA[lk + 4 * j + 0][lr] = v.x;
            sA[lk + 4 * j + 1][lr] = v.y;
            sA[lk + 4 * j + 2][lr] = v.z;
            sA[lk + 4 * j + 3][lr] = v.w;
        }
#pragma unroll
        for (int j = 0; j < 2; j++) {
            float4 v = *(const float4*)&W[(n0 + wn) * 8192 + k0 + wk + 4 * j];
            sW2[wk + 4 * j + 0][wn] = v.x;
            sW2[wk + 4 * j + 1][wn] = v.y;
            sW2[wk + 4 * j + 2][wn] = v.z;
            sW2[wk + 4 * j + 3][wn] = v.w;
        }
        __syncthreads();
#pragma unroll
        for (int k = 0; k < 64; k++) {
            float4 a = *(const float4*)&sA[k][ty * 4];
            float2 w = *(const float2*)&sW2[k][tx * 2];
            acc[0][0] += a.x * w.x; acc[0][1] += a.x * w.y;
            acc[1][0] += a.y * w.x; acc[1][1] += a.y * w.y;
            acc[2][0] += a.z * w.x; acc[2][1] += a.z * w.y;
            acc[3][0] += a.w * w.x; acc[3][1] += a.w * w.y;
        }
        __syncthreads();
    }
#pragma unroll
    for (int r = 0; r < 4; r++)
#pragma unroll
        for (int c = 0; c < 2; c++)
            g_cur3[(row0 + ty * 4 + r) * 256 + n0 + tx * 2 + c] =
                acc[r][c] + bias[n0 + tx * 2 + c];
}

// ---------------------------------------------------------------------------
// Kernel 4: 25-step LIF recurrence through fc2 (256->128) and fc3 (128->10)
// 128 CTAs x 8 batch rows; weights in smem, membrane state in registers
// ---------------------------------------------------------------------------
#define REC_W2S (256 * 129)
#define REC_SMEM_BYTES ((REC_W2S + 1280 + 128 + 16 + 2048 + 1024) * 4)

__global__ void __launch_bounds__(256, 1) rec_kernel(const float* __restrict__ w2,
                                                     const float* __restrict__ b2,
                                                     const float* __restrict__ w3,
                                                     const float* __restrict__ b3,
                                                     float* __restrict__ out) {
    extern __shared__ float sm[];
    float* w2s   = sm;                 // [i*129 + j] transposed + padded
    float* w3s   = w2s + REC_W2S;      // [k*10 + j]
    float* b2s   = w3s + 1280;         // [128]
    float* b3s   = b2s + 128;          // [16]
    float* spk3s = b3s + 16;           // [256][8]
    float* spk4s = spk3s + 2048;       // [128][8]

    const int t = threadIdx.x;
    const int rowbase = blockIdx.x * 8;

    for (int idx = t; idx < 128 * 256; idx += 256) {
        int j = idx >> 8, i = idx & 255;
        w2s[i * 129 + j] = w2[idx];
    }
    for (int idx = t; idx < 1280; idx += 256) {
        int j = idx >> 7, k = idx & 127;
        w3s[k * 10 + j] = w3[idx];
    }
    if (t < 128) b2s[t] = b2[t];
    if (t < 10)  b3s[t] = b3[t];
    __syncthreads();

    // layer-3 state: this thread owns neuron i=t for 8 batch rows
    float mem3[8], c3[8];
#pragma unroll
    for (int r = 0; r < 8; r++) {
        mem3[r] = 0.f;
        c3[r] = g_cur3[(rowbase + r) * 256 + t];
    }
    // layer-4: thread owns neuron j4 for 4 batch rows
    const int j4 = t & 127, rg = t >> 7;
    float mem4[4] = {0.f, 0.f, 0.f, 0.f};
    const float b2v = b2s[j4];
    // layer-5: threads 0..79
    float mem5 = 0.f;
    const int r5 = t / 10, j5 = t % 10;
    const float b3v = (t < 80) ? b3s[j5] : 0.f;

    for (int step = 0; step < NSTEPS; step++) {
        // layer 3 LIF
#pragma unroll
        for (int r = 0; r < 8; r++) {
            float reset = (mem3[r] > 1.f) ? 1.f : 0.f;
            float m = 0.95f * mem3[r] + c3[r] - reset;
            mem3[r] = m;
            spk3s[t * 8 + r] = (m > 1.f) ? 1.f : 0.f;
        }
        __syncthreads();

        // layer 4: cur4 = spk3 @ w2^T + b2 ; LIF
        float a4[4];
#pragma unroll
        for (int r = 0; r < 4; r++) a4[r] = b2v;
#pragma unroll 4
        for (int i = 0; i < 256; i++) {
            float w = w2s[i * 129 + j4];
            float4 s = *(const float4*)&spk3s[i * 8 + rg * 4];
            a4[0] += w * s.x; a4[1] += w * s.y; a4[2] += w * s.z; a4[3] += w * s.w;
        }
#pragma unroll
        for (int r = 0; r < 4; r++) {
            float reset = (mem4[r] > 1.f) ? 1.f : 0.f;
            float m = 0.95f * mem4[r] + a4[r] - reset;
            mem4[r] = m;
            spk4s[j4 * 8 + rg * 4 + r] = (m > 1.f) ? 1.f : 0.f;
        }
        __syncthreads();

        // layer 5: cur5 = spk4 @ w3^T + b3 ; LIF ; emit spikes
        if (t < 80) {
            float a5 = b3v;
#pragma unroll 8
            for (int k = 0; k < 128; k++)
                a5 += w3s[k * 10 + j5] * spk4s[k * 8 + r5];
            float reset = (mem5 > 1.f) ? 1.f : 0.f;
            float m = 0.95f * mem5 + a5 - reset;
            mem5 = m;
            out[(step * 1024 + rowbase + r5) * 10 + j5] = (m > 1.f) ? 1.f : 0.f;
        }
        __syncthreads();
    }
}

// ---------------------------------------------------------------------------
extern "C" void kernel_launch(void* const* d_in, const int* in_sizes, int n_in,
                              void* d_out, int out_size) {
    const float* x       = (const float*)d_in[0];
    const float* conv1_w = (const float*)d_in[1];
    const float* conv1_b = (const float*)d_in[2];
    const float* conv2_w = (const float*)d_in[3];
    const float* conv2_b = (const float*)d_in[4];
    const float* fc1_w   = (const float*)d_in[5];
    const float* fc1_b   = (const float*)d_in[6];
    const float* fc2_w   = (const float*)d_in[7];
    const float* fc2_b   = (const float*)d_in[8];
    const float* fc3_w   = (const float*)d_in[9];
    const float* fc3_b   = (const float*)d_in[10];
    float* out = (float*)d_out;

    cudaFuncSetAttribute(conv2_kernel, cudaFuncAttributeMaxDynamicSharedMemorySize,
                         C2_SMEM_BYTES);
    cudaFuncSetAttribute(rec_kernel, cudaFuncAttributeMaxDynamicSharedMemorySize,
                         REC_SMEM_BYTES);

    conv1_kernel<<<BATCH, 256>>>(x, conv1_w, conv1_b);
    conv2_kernel<<<BATCH, 256, C2_SMEM_BYTES>>>(conv2_w, conv2_b);
    fc1_kernel<<<dim3(16, 8), 256>>>(fc1_w, fc1_b);
    rec_kernel<<<128, 256, REC_SMEM_BYTES>>>(fc2_w, fc2_b, fc3_w, fc3_b, out);
}